// round 7
// baseline (speedup 1.0000x reference)
#include <cuda_runtime.h>
#include <cuda_bf16.h>
#include <cstdint>

#define NUM_USERS 50000
#define NUM_ITEMS 40000
#define EMB 64
#define NNZ 2000000
#define BATCH 1024
#define NCHUNK 313          // ceil(40000/128) column chunks of 128

// ---- scratch (static __device__ globals; no allocation allowed) ----
__device__ float         g_WqT[NUM_ITEMS * 128];     // Wq transposed: [item][128]
__device__ __nv_bfloat16 g_Wpb[NUM_ITEMS * EMB];     // Wp in bf16:   [item][64]
__device__ float         g_hsel[BATCH * 128];        // selected-user h accumulators
__device__ int           g_map[NUM_USERS];           // user -> batch slot (validated by back-check)
__device__ __nv_bfloat16 g_zb[BATCH * EMB];          // z in bf16
__device__ unsigned      g_xbits[BATCH * NCHUNK * 4];// x packed: word v of chunk: bit t = x[c*128+4t+v]
__device__ float         g_sexp[BATCH];
__device__ float         g_sdot[BATCH];
__device__ float         g_scnt[BATCH];
__device__ float         g_kl;

__device__ __forceinline__ unsigned pack_bf162(float lo, float hi) {
    __nv_bfloat162 t = __floats2bfloat162_rn(lo, hi);
    return *(unsigned*)&t;
}

// ---- 1: fused prep: Wq transpose + Wp->bf16 + zero scratch + user map + x bitpack ----
// blocks: [0,5000) transpose | [5000,6250) wpcvt | [6250,6762) hsel zero |
//         [6762] misc | [6763, 6763+40064) x bitpack (8 warp-tasks/block)
__global__ void __launch_bounds__(256)
k_prep(const float* __restrict__ Wq, const float* __restrict__ Wp,
       const int* __restrict__ user, const float* __restrict__ x) {
    __shared__ float tile[32][33];
    int bid = blockIdx.x, tid = threadIdx.x;
    if (bid < 5000) {
        int i0 = (bid % 1250) * 32, k0 = (bid / 1250) * 32;
        int tx = tid & 31, ty = tid >> 5;          // (32,8)
#pragma unroll
        for (int r = 0; r < 32; r += 8)
            tile[ty + r][tx] = Wq[(size_t)(k0 + ty + r) * NUM_ITEMS + i0 + tx];
        __syncthreads();
#pragma unroll
        for (int r = 0; r < 32; r += 8)
            g_WqT[(size_t)(i0 + ty + r) * 128 + k0 + tx] = tile[tx][ty + r];
    } else if (bid < 6250) {
        int i = (bid - 5000) * 256 + tid;          // < 320000 exactly
        const float4* in4 = (const float4*)Wp;
        float4 a = in4[2 * i], b = in4[2 * i + 1];
        uint4 o;
        o.x = pack_bf162(a.x, a.y);
        o.y = pack_bf162(a.z, a.w);
        o.z = pack_bf162(b.x, b.y);
        o.w = pack_bf162(b.z, b.w);
        ((uint4*)g_Wpb)[i] = o;
    } else if (bid < 6762) {
        int i = (bid - 6250) * 256 + tid;          // < 131072 exactly
        g_hsel[i] = 0.f;
    } else if (bid == 6762) {
#pragma unroll
        for (int b = tid; b < BATCH; b += 256) {
            g_sexp[b] = 0.f; g_sdot[b] = 0.f; g_scnt[b] = 0.f;
            g_map[user[b]] = b;                    // racing store; any winner valid
        }
        if (tid == 0) g_kl = 0.f;
    } else {
        // x bitpack: warp-task = (row, chunk); 8 tasks per block
        int w = tid >> 5, lane = tid & 31;
        int task = (bid - 6763) * 8 + w;           // < 320512 exactly (1024*313)
        int row = task / NCHUNK, chunk = task - row * NCHUNK;
        int cbase = chunk * 128 + lane * 4;
        float4 v = make_float4(0.f, 0.f, 0.f, 0.f);
        if (cbase + 3 < NUM_ITEMS)                 // last chunk: 64 valid floats (float4-aligned)
            v = *(const float4*)&x[(size_t)row * NUM_ITEMS + cbase];
        unsigned b0 = __ballot_sync(0xFFFFFFFFu, v.x != 0.f);
        unsigned b1 = __ballot_sync(0xFFFFFFFFu, v.y != 0.f);
        unsigned b2 = __ballot_sync(0xFFFFFFFFu, v.z != 0.f);
        unsigned b3 = __ballot_sync(0xFFFFFFFFu, v.w != 0.f);
        if (lane == 0)
            *(uint4*)&g_xbits[(size_t)(row * NCHUNK + chunk) * 4] = make_uint4(b0, b1, b2, b3);
    }
}

// ---- 2: scatter kept edges (warp-ballot compaction; map validated by back-check) ----
__global__ void k_edges(const float* __restrict__ vals,
                        const int* __restrict__ rows,
                        const int* __restrict__ cols,
                        const int* __restrict__ user) {
    int idx  = blockIdx.x * blockDim.x + threadIdx.x;
    int lane = threadIdx.x & 31;
    int slot = -1, col = 0;
    float val = 0.f;
    if (idx < NNZ) {
        int r = rows[idx];
        int s = g_map[r];
        if ((unsigned)s < BATCH && __ldg(&user[s]) == r) slot = s;
        col = cols[idx];
        val = vals[idx];
    }
    unsigned m = __ballot_sync(0xFFFFFFFFu, slot >= 0);
    while (m) {
        int j = __ffs(m) - 1; m &= m - 1;
        int   c = __shfl_sync(0xFFFFFFFFu, col, j);
        float v = __shfl_sync(0xFFFFFFFFu, val, j);
        int   s = __shfl_sync(0xFFFFFFFFu, slot, j);
        const float* wr = &g_WqT[(size_t)c * 128];
        float* hr = &g_hsel[s * 128];
#pragma unroll
        for (int k = lane; k < 128; k += 32)
            atomicAdd(&hr[k], v * wr[k]);
    }
}

// ---- 3: reparameterize + KL ----
__global__ void k_z(const float* __restrict__ bq,
                    const float* __restrict__ eps,
                    const int* __restrict__ user) {
    int b = blockIdx.x, k = threadIdx.x;   // 64 threads
    int u = user[b];
    int s = g_map[u];
    float mu = g_hsel[s * 128 + k]      + bq[k];
    float lv = g_hsel[s * 128 + 64 + k] + bq[64 + k];
    float z  = mu + eps[u * EMB + k] * __expf(0.5f * lv);
    g_zb[b * EMB + k] = __float2bfloat16(z);
    float t = 1.f + lv - mu * mu - __expf(lv);
#pragma unroll
    for (int o = 16; o > 0; o >>= 1) t += __shfl_down_sync(0xFFFFFFFFu, t, o);
    __shared__ float sm[2];
    if ((threadIdx.x & 31) == 0) sm[threadIdx.x >> 5] = t;
    __syncthreads();
    if (threadIdx.x == 0) atomicAdd(&g_kl, sm[0] + sm[1]);
}

// ---- 4: fused decoder GEMM (bf16 HMMA) + softmax-stats epilogue ----
// Wpb tile in smem; x consumed as loop-invariant bitmask words (2 per result row).
__device__ __forceinline__ void mma16816(float* d, const unsigned* a, const unsigned* b) {
    asm volatile(
        "mma.sync.aligned.m16n8k16.row.col.f32.bf16.bf16.f32 "
        "{%0,%1,%2,%3}, {%4,%5,%6,%7}, {%8,%9}, {%0,%1,%2,%3};\n"
        : "+f"(d[0]), "+f"(d[1]), "+f"(d[2]), "+f"(d[3])
        : "r"(a[0]), "r"(a[1]), "r"(a[2]), "r"(a[3]), "r"(b[0]), "r"(b[1]));
}

#define WP_STRIDE 144   // bytes per smem row: 128 data + 16 pad (bank-conflict-free)

__global__ void __launch_bounds__(256, 2)
k_gemm(const float* __restrict__ bp) {
    __shared__ __align__(16) unsigned char sWp[128 * WP_STRIDE];   // 18 KB

    int w = threadIdx.x >> 5, lane = threadIdx.x & 31;
    int wm = w & 3, wn = w >> 2;                 // 4 warps along M, 2 along N
    int m_base = blockIdx.y * 128 + wm * 32;     // batch rows (in-range)
    int n_blk  = blockIdx.x * 128;
    int n_base = n_blk + wn * 64;                // item cols (tail-predicated)
    int g = lane >> 2, tg = lane & 3;

    // ---- fill smem Wpb tile: rows n_blk..n_blk+127, uint4-coalesced ----
#pragma unroll
    for (int it = 0; it < 4; it++) {
        int i = it * 256 + threadIdx.x;          // 0..1023
        int row = i >> 3, off = i & 7;
        int gr = n_blk + row;
        uint4 v = make_uint4(0u, 0u, 0u, 0u);
        if (gr < NUM_ITEMS) v = *(const uint4*)&g_Wpb[(size_t)gr * 64 + off * 8];
        *(uint4*)&sWp[row * WP_STRIDE + off * 16] = v;
    }

    // ---- A fragments: z tile 32(M) x 64(K), register-resident ----
    unsigned a[2][4][4];
#pragma unroll
    for (int mf = 0; mf < 2; mf++) {
        int r0 = m_base + mf * 16 + g;
#pragma unroll
        for (int kf = 0; kf < 4; kf++) {
            int kb = kf * 16 + tg * 2;
            a[mf][kf][0] = *(const unsigned*)&g_zb[(r0)     * 64 + kb];
            a[mf][kf][1] = *(const unsigned*)&g_zb[(r0 + 8) * 64 + kb];
            a[mf][kf][2] = *(const unsigned*)&g_zb[(r0)     * 64 + kb + 8];
            a[mf][kf][3] = *(const unsigned*)&g_zb[(r0 + 8) * 64 + kb + 8];
        }
    }

    // ---- x bitmask words: loop-invariant per result row ----
    // col c = n_base + nf*8 + tg*2 (+1); within chunk: o = c - n_blk,
    // word v = o&3 = (tg*2)&3 = 2*(tg&1) (+1 for second col), bit t = o>>2 = 2*nf + (tg>>1)
    int v0  = (tg & 1) * 2;
    int tsh = tg >> 1;
    // (wn*64)>>2 = wn*16 extra bit offset: o includes wn*64 → t = 16*wn + 2*nf + tsh
    int tofs = wn * 16 + tsh;
    unsigned xw0[4], xw1[4];
#pragma unroll
    for (int li = 0; li < 4; li++) {
        int row = m_base + (li >> 1) * 16 + (li & 1) * 8 + g;
        uint2 xv = *(const uint2*)&g_xbits[(size_t)(row * NCHUNK + blockIdx.x) * 4 + v0];
        xw0[li] = xv.x; xw1[li] = xv.y;
    }
    __syncthreads();

    float sexp[4] = {0, 0, 0, 0}, sdot[4] = {0, 0, 0, 0}, scnt[4] = {0, 0, 0, 0};

#pragma unroll
    for (int nf = 0; nf < 8; nf++) {
        // B fragments from smem (conflict-free LDS)
        int rloc = wn * 64 + nf * 8 + g;         // local smem row
        unsigned bf[4][2];
#pragma unroll
        for (int kf = 0; kf < 4; kf++) {
            bf[kf][0] = *(const unsigned*)&sWp[rloc * WP_STRIDE + kf * 32 + tg * 4];
            bf[kf][1] = *(const unsigned*)&sWp[rloc * WP_STRIDE + kf * 32 + tg * 4 + 16];
        }

        float d[2][4] = {{0, 0, 0, 0}, {0, 0, 0, 0}};
#pragma unroll
        for (int mf = 0; mf < 2; mf++)
#pragma unroll
            for (int kf = 0; kf < 4; kf++)
                mma16816(d[mf], a[mf][kf], bf[kf]);

        int c0 = n_base + nf * 8 + tg * 2;
        int t  = tofs + nf * 2;                  // bit position in xw words
        if (c0 < NUM_ITEMS) {
            float2 bpv = *(const float2*)&bp[c0];
#pragma unroll
            for (int mf = 0; mf < 2; mf++)
#pragma unroll
                for (int h = 0; h < 2; h++) {
                    int li = mf * 2 + h;
                    float v0f = d[mf][h * 2 + 0] + bpv.x;
                    float v1f = d[mf][h * 2 + 1] + bpv.y;
                    sexp[li] += __expf(v0f) + __expf(v1f);
                    if ((xw0[li] >> t) & 1) { sdot[li] += v0f; scnt[li] += 1.f; }
                    if ((xw1[li] >> t) & 1) { sdot[li] += v1f; scnt[li] += 1.f; }
                }
        }
    }

    // reduce across the 4 threads of each group (tg), then atomics per row
#pragma unroll
    for (int li = 0; li < 4; li++) {
        float se = sexp[li], sd = sdot[li], sc = scnt[li];
#pragma unroll
        for (int o = 1; o < 4; o <<= 1) {
            se += __shfl_xor_sync(0xFFFFFFFFu, se, o);
            sd += __shfl_xor_sync(0xFFFFFFFFu, sd, o);
            sc += __shfl_xor_sync(0xFFFFFFFFu, sc, o);
        }
        if (tg == 0) {
            int row = m_base + (li >> 1) * 16 + (li & 1) * 8 + g;
            atomicAdd(&g_sexp[row], se);
            atomicAdd(&g_sdot[row], sd);
            atomicAdd(&g_scnt[row], sc);
        }
    }
}

// ---- 5: final reduction ----
__global__ void k_final(float* __restrict__ out) {
    __shared__ float sm[256];
    float acc = 0.f;
    for (int r = threadIdx.x; r < BATCH; r += 256)
        acc += g_scnt[r] * logf(g_sexp[r]) - g_sdot[r];
    sm[threadIdx.x] = acc;
    __syncthreads();
    for (int o = 128; o > 0; o >>= 1) {
        if (threadIdx.x < o) sm[threadIdx.x] += sm[threadIdx.x + o];
        __syncthreads();
    }
    if (threadIdx.x == 0) {
        out[0] = sm[0] / (float)BATCH;
        out[1] = -0.5f * g_kl / (float)BATCH;
    }
}

extern "C" void kernel_launch(void* const* d_in, const int* in_sizes, int n_in,
                              void* d_out, int out_size) {
    const float* graph_vals = (const float*)d_in[0];
    const float* Wq         = (const float*)d_in[1];
    const float* bq         = (const float*)d_in[2];
    const float* Wp         = (const float*)d_in[3];
    const float* bp         = (const float*)d_in[4];
    const float* x          = (const float*)d_in[5];
    const float* eps        = (const float*)d_in[6];
    const int*   graph_rows = (const int*)d_in[7];
    const int*   graph_cols = (const int*)d_in[8];
    const int*   user       = (const int*)d_in[9];
    float* out = (float*)d_out;

    k_prep<<<6763 + 40064, 256>>>(Wq, Wp, user, x);
    k_edges<<<(NNZ + 255) / 256, 256>>>(graph_vals, graph_rows, graph_cols, user);
    k_z<<<BATCH, 64>>>(bq, eps, user);
    {
        dim3 grid((NUM_ITEMS + 127) / 128, BATCH / 128);
        k_gemm<<<grid, 256>>>(bp);
    }
    k_final<<<1, 256>>>(out);
}

// round 8
// speedup vs baseline: 1.4479x; 1.4479x over previous
#include <cuda_runtime.h>
#include <cuda_bf16.h>
#include <cstdint>

#define NUM_USERS 50000
#define NUM_ITEMS 40000
#define EMB 64
#define NNZ 2000000
#define BATCH 1024

// ---- scratch (static __device__ globals; no allocation allowed) ----
__device__ float         g_WqT[NUM_ITEMS * 128];     // Wq transposed: [item][128]
__device__ __nv_bfloat16 g_Wpb[NUM_ITEMS * EMB];     // Wp in bf16:   [item][64]
__device__ float         g_hsel[BATCH * 128];        // selected-user h accumulators
__device__ int           g_map[NUM_USERS];           // user -> batch slot (validated by back-check)
__device__ __nv_bfloat16 g_zb[BATCH * EMB];          // z in bf16
__device__ float         g_sexp[BATCH];
__device__ float         g_sdot[BATCH];
__device__ float         g_scnt[BATCH];
__device__ float         g_kl;

__device__ __forceinline__ unsigned pack_bf162(float lo, float hi) {
    __nv_bfloat162 t = __floats2bfloat162_rn(lo, hi);
    return *(unsigned*)&t;
}

// ---- 1: fused prep: Wq transpose + Wp->bf16 + zero scratch + user map ----
__global__ void __launch_bounds__(256)
k_prep(const float* __restrict__ Wq, const float* __restrict__ Wp,
       const int* __restrict__ user) {
    __shared__ float tile[32][33];
    int bid = blockIdx.x, tid = threadIdx.x;
    if (bid < 5000) {
        int i0 = (bid % 1250) * 32, k0 = (bid / 1250) * 32;
        int tx = tid & 31, ty = tid >> 5;          // (32,8)
#pragma unroll
        for (int r = 0; r < 32; r += 8)
            tile[ty + r][tx] = Wq[(size_t)(k0 + ty + r) * NUM_ITEMS + i0 + tx];
        __syncthreads();
#pragma unroll
        for (int r = 0; r < 32; r += 8)
            g_WqT[(size_t)(i0 + ty + r) * 128 + k0 + tx] = tile[tx][ty + r];
    } else if (bid < 6250) {
        int i = (bid - 5000) * 256 + tid;          // < 320000 exactly
        const float4* in4 = (const float4*)Wp;
        float4 a = in4[2 * i], b = in4[2 * i + 1];
        uint4 o;
        o.x = pack_bf162(a.x, a.y);
        o.y = pack_bf162(a.z, a.w);
        o.z = pack_bf162(b.x, b.y);
        o.w = pack_bf162(b.z, b.w);
        ((uint4*)g_Wpb)[i] = o;
    } else if (bid < 6762) {
        int i = (bid - 6250) * 256 + tid;          // < 131072 exactly
        g_hsel[i] = 0.f;
    } else {
#pragma unroll
        for (int b = tid; b < BATCH; b += 256) {
            g_sexp[b] = 0.f; g_sdot[b] = 0.f; g_scnt[b] = 0.f;
            g_map[user[b]] = b;                    // racing store; any winner valid
        }
        if (tid == 0) g_kl = 0.f;
    }
}

// ---- 2: scatter kept edges (warp-ballot compaction; map validated by back-check) ----
__global__ void k_edges(const float* __restrict__ vals,
                        const int* __restrict__ rows,
                        const int* __restrict__ cols,
                        const int* __restrict__ user) {
    int idx  = blockIdx.x * blockDim.x + threadIdx.x;
    int lane = threadIdx.x & 31;
    int slot = -1, col = 0;
    float val = 0.f;
    if (idx < NNZ) {
        int r = rows[idx];
        int s = g_map[r];
        if ((unsigned)s < BATCH && __ldg(&user[s]) == r) slot = s;
        col = cols[idx];
        val = vals[idx];
    }
    unsigned m = __ballot_sync(0xFFFFFFFFu, slot >= 0);
    while (m) {
        int j = __ffs(m) - 1; m &= m - 1;
        int   c = __shfl_sync(0xFFFFFFFFu, col, j);
        float v = __shfl_sync(0xFFFFFFFFu, val, j);
        int   s = __shfl_sync(0xFFFFFFFFu, slot, j);
        const float* wr = &g_WqT[(size_t)c * 128];
        float* hr = &g_hsel[s * 128];
#pragma unroll
        for (int k = lane; k < 128; k += 32)
            atomicAdd(&hr[k], v * wr[k]);
    }
}

// ---- 3: reparameterize + KL ----
__global__ void k_z(const float* __restrict__ bq,
                    const float* __restrict__ eps,
                    const int* __restrict__ user) {
    int b = blockIdx.x, k = threadIdx.x;   // 64 threads
    int u = user[b];
    int s = g_map[u];
    float mu = g_hsel[s * 128 + k]      + bq[k];
    float lv = g_hsel[s * 128 + 64 + k] + bq[64 + k];
    float z  = mu + eps[u * EMB + k] * __expf(0.5f * lv);
    g_zb[b * EMB + k] = __float2bfloat16(z);
    float t = 1.f + lv - mu * mu - __expf(lv);
#pragma unroll
    for (int o = 16; o > 0; o >>= 1) t += __shfl_down_sync(0xFFFFFFFFu, t, o);
    __shared__ float sm[2];
    if ((threadIdx.x & 31) == 0) sm[threadIdx.x >> 5] = t;
    __syncthreads();
    if (threadIdx.x == 0) atomicAdd(&g_kl, sm[0] + sm[1]);
}

// ---- 4: fused decoder GEMM (bf16 HMMA) + softmax-stats epilogue ----
// Wpb tile in smem; x tile loaded coalesced, ballot-packed to smem bitmask
// in-kernel (x read ONCE, overlapped with MMA/MUFU work).
__device__ __forceinline__ void mma16816(float* d, const unsigned* a, const unsigned* b) {
    asm volatile(
        "mma.sync.aligned.m16n8k16.row.col.f32.bf16.bf16.f32 "
        "{%0,%1,%2,%3}, {%4,%5,%6,%7}, {%8,%9}, {%0,%1,%2,%3};\n"
        : "+f"(d[0]), "+f"(d[1]), "+f"(d[2]), "+f"(d[3])
        : "r"(a[0]), "r"(a[1]), "r"(a[2]), "r"(a[3]), "r"(b[0]), "r"(b[1]));
}

#define WP_STRIDE 144   // bytes per smem row: 128 data + 16 pad (bank-conflict-free)

__global__ void __launch_bounds__(256, 3)
k_gemm(const float* __restrict__ bp, const float* __restrict__ x) {
    __shared__ __align__(16) unsigned char sWp[128 * WP_STRIDE];   // 18 KB
    __shared__ __align__(16) unsigned sX[128 * 4];                 // 2 KB bitmask

    int w = threadIdx.x >> 5, lane = threadIdx.x & 31;
    int wm = w & 3, wn = w >> 2;                 // 4 warps along M, 2 along N
    int m_blk  = blockIdx.y * 128;
    int m_base = m_blk + wm * 32;                // batch rows (in-range)
    int n_blk  = blockIdx.x * 128;
    int n_base = n_blk + wn * 64;                // item cols (tail-predicated)
    int g = lane >> 2, tg = lane & 3;

    // ---- fill smem Wpb tile: rows n_blk..n_blk+127, uint4-coalesced ----
#pragma unroll
    for (int it = 0; it < 4; it++) {
        int i = it * 256 + threadIdx.x;          // 0..1023
        int row = i >> 3, off = i & 7;
        int gr = n_blk + row;
        uint4 v = make_uint4(0u, 0u, 0u, 0u);
        if (gr < NUM_ITEMS) v = *(const uint4*)&g_Wpb[(size_t)gr * 64 + off * 8];
        *(uint4*)&sWp[row * WP_STRIDE + off * 16] = v;
    }

    // ---- load + pack x tile [128 rows x 128 cols] to smem bits ----
    // warp handles one row per iter: lane reads x[row][n_blk + lane*4 .. +3]
    // word v, bit t  <=>  col_in_chunk = 4t + v
    {
        int cb = n_blk + lane * 4;
        bool cok = (cb + 3) < NUM_ITEMS;         // tail chunk: lanes 0..15 valid
#pragma unroll
        for (int it = 0; it < 16; it++) {
            int row = it * 8 + w;                // 0..127
            float4 v = make_float4(0.f, 0.f, 0.f, 0.f);
            if (cok) v = __ldcs((const float4*)&x[(size_t)(m_blk + row) * NUM_ITEMS + cb]);
            unsigned b0 = __ballot_sync(0xFFFFFFFFu, v.x != 0.f);
            unsigned b1 = __ballot_sync(0xFFFFFFFFu, v.y != 0.f);
            unsigned b2 = __ballot_sync(0xFFFFFFFFu, v.z != 0.f);
            unsigned b3 = __ballot_sync(0xFFFFFFFFu, v.w != 0.f);
            if (lane == 0) *(uint4*)&sX[row * 4] = make_uint4(b0, b1, b2, b3);
        }
    }

    // ---- A fragments: z tile 32(M) x 64(K), register-resident ----
    unsigned a[2][4][4];
#pragma unroll
    for (int mf = 0; mf < 2; mf++) {
        int r0 = m_base + mf * 16 + g;
#pragma unroll
        for (int kf = 0; kf < 4; kf++) {
            int kb = kf * 16 + tg * 2;
            a[mf][kf][0] = *(const unsigned*)&g_zb[(r0)     * 64 + kb];
            a[mf][kf][1] = *(const unsigned*)&g_zb[(r0 + 8) * 64 + kb];
            a[mf][kf][2] = *(const unsigned*)&g_zb[(r0)     * 64 + kb + 8];
            a[mf][kf][3] = *(const unsigned*)&g_zb[(r0 + 8) * 64 + kb + 8];
        }
    }

    __syncthreads();

    // ---- x bitmask words: loop-invariant per result row (from smem) ----
    // col c = n_base + nf*8 + tg*2 (+1); o = c - n_blk;
    // word = o&3 = 2*(tg&1) (+1 for hi col), bit t = o>>2 = 16*wn + 2*nf + (tg>>1)
    int v0   = (tg & 1) * 2;
    int tofs = wn * 16 + (tg >> 1);
    unsigned xw0[4], xw1[4];
#pragma unroll
    for (int li = 0; li < 4; li++) {
        int local = wm * 32 + (li >> 1) * 16 + (li & 1) * 8 + g;
        uint2 xv = *(const uint2*)&sX[local * 4 + v0];
        xw0[li] = xv.x; xw1[li] = xv.y;
    }

    float sexp[4] = {0, 0, 0, 0}, sdot[4] = {0, 0, 0, 0}, scnt[4] = {0, 0, 0, 0};

#pragma unroll
    for (int nf = 0; nf < 8; nf++) {
        // B fragments from smem (conflict-free LDS)
        int rloc = wn * 64 + nf * 8 + g;         // local smem row
        unsigned bf[4][2];
#pragma unroll
        for (int kf = 0; kf < 4; kf++) {
            bf[kf][0] = *(const unsigned*)&sWp[rloc * WP_STRIDE + kf * 32 + tg * 4];
            bf[kf][1] = *(const unsigned*)&sWp[rloc * WP_STRIDE + kf * 32 + tg * 4 + 16];
        }

        float d[2][4] = {{0, 0, 0, 0}, {0, 0, 0, 0}};
#pragma unroll
        for (int mf = 0; mf < 2; mf++)
#pragma unroll
            for (int kf = 0; kf < 4; kf++)
                mma16816(d[mf], a[mf][kf], bf[kf]);

        int c0 = n_base + nf * 8 + tg * 2;
        int t  = tofs + nf * 2;                  // bit position in xw words
        if (c0 < NUM_ITEMS) {
            float2 bpv = *(const float2*)&bp[c0];
#pragma unroll
            for (int mf = 0; mf < 2; mf++)
#pragma unroll
                for (int h = 0; h < 2; h++) {
                    int li = mf * 2 + h;
                    float v0f = d[mf][h * 2 + 0] + bpv.x;
                    float v1f = d[mf][h * 2 + 1] + bpv.y;
                    sexp[li] += __expf(v0f) + __expf(v1f);
                    if ((xw0[li] >> t) & 1) { sdot[li] += v0f; scnt[li] += 1.f; }
                    if ((xw1[li] >> t) & 1) { sdot[li] += v1f; scnt[li] += 1.f; }
                }
        }
    }

    // reduce across the 4 threads of each group (tg), then atomics per row
#pragma unroll
    for (int li = 0; li < 4; li++) {
        float se = sexp[li], sd = sdot[li], sc = scnt[li];
#pragma unroll
        for (int o = 1; o < 4; o <<= 1) {
            se += __shfl_xor_sync(0xFFFFFFFFu, se, o);
            sd += __shfl_xor_sync(0xFFFFFFFFu, sd, o);
            sc += __shfl_xor_sync(0xFFFFFFFFu, sc, o);
        }
        if (tg == 0) {
            int row = m_base + (li >> 1) * 16 + (li & 1) * 8 + g;
            atomicAdd(&g_sexp[row], se);
            atomicAdd(&g_sdot[row], sd);
            atomicAdd(&g_scnt[row], sc);
        }
    }
}

// ---- 5: final reduction ----
__global__ void k_final(float* __restrict__ out) {
    __shared__ float sm[256];
    float acc = 0.f;
    for (int r = threadIdx.x; r < BATCH; r += 256)
        acc += g_scnt[r] * logf(g_sexp[r]) - g_sdot[r];
    sm[threadIdx.x] = acc;
    __syncthreads();
    for (int o = 128; o > 0; o >>= 1) {
        if (threadIdx.x < o) sm[threadIdx.x] += sm[threadIdx.x + o];
        __syncthreads();
    }
    if (threadIdx.x == 0) {
        out[0] = sm[0] / (float)BATCH;
        out[1] = -0.5f * g_kl / (float)BATCH;
    }
}

extern "C" void kernel_launch(void* const* d_in, const int* in_sizes, int n_in,
                              void* d_out, int out_size) {
    const float* graph_vals = (const float*)d_in[0];
    const float* Wq         = (const float*)d_in[1];
    const float* bq         = (const float*)d_in[2];
    const float* Wp         = (const float*)d_in[3];
    const float* bp         = (const float*)d_in[4];
    const float* x          = (const float*)d_in[5];
    const float* eps        = (const float*)d_in[6];
    const int*   graph_rows = (const int*)d_in[7];
    const int*   graph_cols = (const int*)d_in[8];
    const int*   user       = (const int*)d_in[9];
    float* out = (float*)d_out;

    k_prep<<<6763, 256>>>(Wq, Wp, user);
    k_edges<<<(NNZ + 255) / 256, 256>>>(graph_vals, graph_rows, graph_cols, user);
    k_z<<<BATCH, 64>>>(bq, eps, user);
    {
        dim3 grid((NUM_ITEMS + 127) / 128, BATCH / 128);
        k_gemm<<<grid, 256>>>(bp, x);
    }
    k_final<<<1, 256>>>(out);
}